// round 11
// baseline (speedup 1.0000x reference)
#include <cuda_runtime.h>

// MemoryUpdater: B=1024 edges, N=1024 nodes, D=256.
// [zero(sums,cnt) + MLP1(direct gather) || GRU-gh] tf32
//   -> MLP2 (+atomic segment sum +counts) -> GRU-gi tf32 -> gate/blend.
// 4 launches total.

#define Bq 1024
#define Nn 1024
#define Dd 256
#define K1 768   // 3*D

// Scratch (device globals; no allocs allowed)
__device__ __align__(16) float g_H[2 * Bq * Dd];   // MLP hidden   [2048,256]
__device__ __align__(16) float g_sums[Nn * Dd];    // segment sums [1024,256]
__device__ __align__(16) float g_cnt[Nn];          // segment counts
__device__ __align__(16) float g_gi[Nn * K1];      // agg @ wih^T + bih
__device__ __align__(16) float g_gh[Nn * K1];      // mem @ whh^T + bhh

// ---------------------------------------------------------------------------
// tf32 mma.sync NT GEMM core: C[64,64] block of A[M,K] * W[N,K]^T.
// 128 threads = 4 warps (2x2), warp tile 32x32 = 2 x m16 by 4 x n8.
// Double-buffered smem, one __syncthreads per K-chunk; LDG k+1 before MMA of k.
// A rows come from three pre-offset pointers (region by kk) so MLP1 gathers
// [mem[n0] | mem[n1] | dt[b,n0]] with no materialized X.
#define PAD 36   // words; 144B row stride: rows 16B-aligned, frag LDS conflict-free

__device__ __forceinline__ unsigned f2tf(float x) {
    unsigned r;
    asm("cvt.rna.tf32.f32 %0, %1;" : "=r"(r) : "f"(x));
    return r;
}

__device__ __forceinline__ void mma_tf32(float c[4], unsigned a0, unsigned a1,
                                         unsigned a2, unsigned a3,
                                         unsigned b0, unsigned b1) {
    asm volatile(
        "mma.sync.aligned.m16n8k8.row.col.f32.tf32.tf32.f32 "
        "{%0,%1,%2,%3}, {%4,%5,%6,%7}, {%8,%9}, {%0,%1,%2,%3};\n"
        : "+f"(c[0]), "+f"(c[1]), "+f"(c[2]), "+f"(c[3])
        : "r"(a0), "r"(a1), "r"(a2), "r"(a3), "r"(b0), "r"(b1));
}

struct APtrs { const float* p0[4]; const float* p1[4]; const float* p2[4]; };
struct WPtrs { const float* p[4]; };

__device__ __forceinline__ const float* asel(const APtrs& A, int i, int kk) {
    // kk region uniform per chunk (chunks are 32-wide, regions 256-aligned)
    const float* q = A.p0[i] + kk;
    if (kk >= 256) q = A.p1[i] + (kk - 256);
    if (kk >= 512) q = A.p2[i] + (kk - 512);
    return q;
}

// rsv: per-row-group scale (row group i = arow + 16*i)
__device__ __forceinline__ void gemm_core(const APtrs& A, const WPtrs& Wp, int K,
                                          float4 rsv, float acc[2][4][4]) {
    __shared__ __align__(16) unsigned As[2][64 * PAD];
    __shared__ __align__(16) unsigned Ws[2][64 * PAD];
    int t    = threadIdx.x;
    int lane = t & 31;
    int w    = t >> 5;
    int gid  = lane >> 2;   // 0..7
    int tig  = lane & 3;    // 0..3
    int w_m  = w & 1;
    int w_n  = w >> 1;
    int arow = t >> 3;          // 0..15
    int acol = (t & 7) << 2;    // 0..28

    float4 ra[4], rw[4];
#pragma unroll
    for (int i = 0; i < 4; i++) {
        ra[i] = *(const float4*)asel(A, i, 0);
        rw[i] = *(const float4*)(Wp.p[i]);
    }
#pragma unroll
    for (int i = 0; i < 4; i++) {
        int r = arow + 16 * i;
        float s = (i == 0) ? rsv.x : (i == 1) ? rsv.y : (i == 2) ? rsv.z : rsv.w;
        *(uint4*)&As[0][r * PAD + acol] = make_uint4(
            f2tf(ra[i].x * s), f2tf(ra[i].y * s), f2tf(ra[i].z * s), f2tf(ra[i].w * s));
        *(uint4*)&Ws[0][r * PAD + acol] = make_uint4(
            f2tf(rw[i].x), f2tf(rw[i].y), f2tf(rw[i].z), f2tf(rw[i].w));
    }
    __syncthreads();

    int p = 0;
    for (int kk = 0; kk < K; kk += 32) {
        bool more = (kk + 32 < K);
        if (more) {
            int kn = kk + 32;
#pragma unroll
            for (int i = 0; i < 4; i++) {
                ra[i] = *(const float4*)asel(A, i, kn);
                rw[i] = *(const float4*)(Wp.p[i] + kn);
            }
        }
#pragma unroll
        for (int ks = 0; ks < 4; ks++) {
            int k0 = ks * 8;
            unsigned a[2][4], b[4][2];
#pragma unroll
            for (int mi = 0; mi < 2; mi++) {
                int r0 = w_m * 32 + mi * 16;
                a[mi][0] = As[p][(r0 + gid)     * PAD + k0 + tig];
                a[mi][1] = As[p][(r0 + gid + 8) * PAD + k0 + tig];
                a[mi][2] = As[p][(r0 + gid)     * PAD + k0 + tig + 4];
                a[mi][3] = As[p][(r0 + gid + 8) * PAD + k0 + tig + 4];
            }
#pragma unroll
            for (int ni = 0; ni < 4; ni++) {
                int c0 = w_n * 32 + ni * 8;
                b[ni][0] = Ws[p][(c0 + gid) * PAD + k0 + tig];
                b[ni][1] = Ws[p][(c0 + gid) * PAD + k0 + tig + 4];
            }
#pragma unroll
            for (int mi = 0; mi < 2; mi++)
#pragma unroll
                for (int ni = 0; ni < 4; ni++)
                    mma_tf32(acc[mi][ni], a[mi][0], a[mi][1], a[mi][2], a[mi][3],
                             b[ni][0], b[ni][1]);
        }
        if (more) {
            int q = p ^ 1;
#pragma unroll
            for (int i = 0; i < 4; i++) {
                int r = arow + 16 * i;
                float s = (i == 0) ? rsv.x : (i == 1) ? rsv.y : (i == 2) ? rsv.z : rsv.w;
                *(uint4*)&As[q][r * PAD + acol] = make_uint4(
                    f2tf(ra[i].x * s), f2tf(ra[i].y * s), f2tf(ra[i].z * s), f2tf(ra[i].w * s));
                *(uint4*)&Ws[q][r * PAD + acol] = make_uint4(
                    f2tf(rw[i].x), f2tf(rw[i].y), f2tf(rw[i].z), f2tf(rw[i].w));
            }
            __syncthreads();
            p = q;
        }
    }
}

#define EPILOGUE_IDS                                           \
    int lane = threadIdx.x & 31, w = threadIdx.x >> 5;         \
    int gid = lane >> 2, tig = lane & 3;                       \
    int w_m = w & 1, w_n = w >> 1;

#define F4_ONE make_float4(1.f, 1.f, 1.f, 1.f)

// Fused: all blocks first zero a disjoint slice of g_sums/g_cnt (done before
// gemm2 launch by stream order). Then:
//   blocks [0,128): MLP1 direct-gather: g_H = relu(X @ W1^T + b1),
//                   X row r = [mem[n0] | mem[n1] | dt[b,n0]].
//   blocks [128,320): g_gh = memory @ whh^T + bhh. Independent work.
__global__ void __launch_bounds__(128, 1)
mlp1_gh_kernel(const float* __restrict__ sw1, const float* __restrict__ sb1,
               const float* __restrict__ tw1, const float* __restrict__ tb1,
               const float* __restrict__ memory,
               const float* __restrict__ whh, const float* __restrict__ bhh,
               const int* __restrict__ src, const int* __restrict__ tgt,
               const float* __restrict__ dt) {
    int bid  = blockIdx.x;
    int t    = threadIdx.x;
    // folded zeroing: 256 blocks x 128 thr x 2 float4 = 65536 float4 = g_sums
    if (bid < 256) {
        float4 z = make_float4(0.f, 0.f, 0.f, 0.f);
        ((float4*)g_sums)[bid * 256 + t]       = z;
        ((float4*)g_sums)[bid * 256 + 128 + t] = z;
        if (bid < 8) g_cnt[bid * 128 + t] = 0.0f;
    }
    int arow = t >> 3;
    int acol = (t & 7) << 2;
    if (bid < 128) {
        int bm = (bid & 31) * 64, bn = (bid >> 5) * 64;
        const float* W    = (bm < Bq) ? sw1 : tw1;
        const float* bias = (bm < Bq) ? sb1 : tb1;
        APtrs ap; WPtrs wp;
#pragma unroll
        for (int i = 0; i < 4; i++) {
            int r = bm + arow + 16 * i;           // edge row 0..2047
            bool first = r < Bq;
            int b  = first ? r : r - Bq;
            int s  = src[b];
            int g  = tgt[b];
            int n0 = first ? s : g;
            int n1 = first ? g : s;
            ap.p0[i] = memory + (size_t)n0 * Dd + acol;
            ap.p1[i] = memory + (size_t)n1 * Dd + acol;
            ap.p2[i] = dt + ((size_t)b * Nn + n0) * Dd + acol;
            wp.p[i]  = W + (size_t)(bn + arow + 16 * i) * K1 + acol;
        }
        float acc[2][4][4] = {};
        gemm_core(ap, wp, K1, F4_ONE, acc);
        EPILOGUE_IDS
#pragma unroll
        for (int mi = 0; mi < 2; mi++) {
            int r0 = bm + w_m * 32 + mi * 16 + gid;
#pragma unroll
            for (int ni = 0; ni < 4; ni++) {
                int c0 = bn + w_n * 32 + ni * 8 + tig * 2;
                float b0 = bias[c0], b1 = bias[c0 + 1];
                g_H[(size_t)r0 * Dd + c0]           = fmaxf(acc[mi][ni][0] + b0, 0.0f);
                g_H[(size_t)r0 * Dd + c0 + 1]       = fmaxf(acc[mi][ni][1] + b1, 0.0f);
                g_H[(size_t)(r0 + 8) * Dd + c0]     = fmaxf(acc[mi][ni][2] + b0, 0.0f);
                g_H[(size_t)(r0 + 8) * Dd + c0 + 1] = fmaxf(acc[mi][ni][3] + b1, 0.0f);
            }
        }
    } else {
        int j = bid - 128;                       // 0..191 -> 16 x 12 tiles
        int bm = (j & 15) * 64, bn = (j >> 4) * 64;
        APtrs ap; WPtrs wp;
#pragma unroll
        for (int i = 0; i < 4; i++) {
            const float* base = memory + (size_t)(bm + arow + 16 * i) * Dd + acol;
            ap.p0[i] = base; ap.p1[i] = base; ap.p2[i] = base;  // K=256: only p0 used
            wp.p[i]  = whh + (size_t)(bn + arow + 16 * i) * Dd + acol;
        }
        float acc[2][4][4] = {};
        gemm_core(ap, wp, Dd, F4_ONE, acc);
        EPILOGUE_IDS
#pragma unroll
        for (int mi = 0; mi < 2; mi++) {
            int r0 = bm + w_m * 32 + mi * 16 + gid;
#pragma unroll
            for (int ni = 0; ni < 4; ni++) {
                int c0 = bn + w_n * 32 + ni * 8 + tig * 2;
                float b0 = bhh[c0], b1 = bhh[c0 + 1];
                g_gh[(size_t)r0 * K1 + c0]           = acc[mi][ni][0] + b0;
                g_gh[(size_t)r0 * K1 + c0 + 1]       = acc[mi][ni][1] + b1;
                g_gh[(size_t)(r0 + 8) * K1 + c0]     = acc[mi][ni][2] + b0;
                g_gh[(size_t)(r0 + 8) * K1 + c0 + 1] = acc[mi][ni][3] + b1;
            }
        }
    }
}

// MLP layer 2 + segment-sum scatter (float2 atomics) + node counts (bn==0 column).
__global__ void __launch_bounds__(128, 1)
gemm2_kernel(const float* __restrict__ sw2, const float* __restrict__ sb2,
             const float* __restrict__ tw2, const float* __restrict__ tb2,
             const int* __restrict__ src, const int* __restrict__ tgt) {
    int bm = blockIdx.x * 64, bn = blockIdx.y * 64;
    int t    = threadIdx.x;
    int arow = t >> 3;
    int acol = (t & 7) << 2;
    if (blockIdx.y == 0 && t < 64) {   // counts: once per row
        int r = bm + t;
        int node = (r < Bq) ? src[r] : tgt[r - Bq];
        atomicAdd(&g_cnt[node], 1.0f);
    }
    const float* W    = (bm < Bq) ? sw2 : tw2;
    const float* bias = (bm < Bq) ? sb2 : tb2;
    APtrs ap; WPtrs wp;
#pragma unroll
    for (int i = 0; i < 4; i++) {
        const float* base = g_H + (size_t)(bm + arow + 16 * i) * Dd + acol;
        ap.p0[i] = base; ap.p1[i] = base; ap.p2[i] = base;
        wp.p[i]  = W + (size_t)(bn + arow + 16 * i) * Dd + acol;
    }
    float acc[2][4][4] = {};
    gemm_core(ap, wp, Dd, F4_ONE, acc);
    EPILOGUE_IDS
#pragma unroll
    for (int mi = 0; mi < 2; mi++) {
        int r0 = bm + w_m * 32 + mi * 16 + gid;
#pragma unroll
        for (int rr = 0; rr < 2; rr++) {
            int r = r0 + rr * 8;
            int node = (r < Bq) ? src[r] : tgt[r - Bq];
            float* base = g_sums + (size_t)node * Dd;
#pragma unroll
            for (int ni = 0; ni < 4; ni++) {
                int c0 = bn + w_n * 32 + ni * 8 + tig * 2;
                float2 v = make_float2(acc[mi][ni][rr * 2]     + bias[c0],
                                       acc[mi][ni][rr * 2 + 1] + bias[c0 + 1]);
                atomicAdd((float2*)&base[c0], v);
            }
        }
    }
}

// GRU gi: g_gi = (sums/max(cnt,1)) @ wih^T + bih  (row scale in registers)
__global__ void __launch_bounds__(128, 1)
gi_kernel(const float* __restrict__ wih, const float* __restrict__ bih) {
    int bm = blockIdx.x * 64, bn = blockIdx.y * 64;
    int t    = threadIdx.x;
    int arow = t >> 3;
    int acol = (t & 7) << 2;
    APtrs ap; WPtrs wp;
    float4 rsv;
    float* rsp = (float*)&rsv;
#pragma unroll
    for (int i = 0; i < 4; i++) {
        int r = bm + arow + 16 * i;
        rsp[i] = 1.0f / fmaxf(g_cnt[r], 1.0f);
        const float* base = g_sums + (size_t)r * Dd + acol;
        ap.p0[i] = base; ap.p1[i] = base; ap.p2[i] = base;
        wp.p[i]  = wih + (size_t)(bn + arow + 16 * i) * Dd + acol;
    }
    float acc[2][4][4] = {};
    gemm_core(ap, wp, Dd, rsv, acc);
    EPILOGUE_IDS
#pragma unroll
    for (int mi = 0; mi < 2; mi++) {
        int r0 = bm + w_m * 32 + mi * 16 + gid;
#pragma unroll
        for (int ni = 0; ni < 4; ni++) {
            int c0 = bn + w_n * 32 + ni * 8 + tig * 2;
            float b0 = bih[c0], b1 = bih[c0 + 1];
            g_gi[(size_t)r0 * K1 + c0]           = acc[mi][ni][0] + b0;
            g_gi[(size_t)r0 * K1 + c0 + 1]       = acc[mi][ni][1] + b1;
            g_gi[(size_t)(r0 + 8) * K1 + c0]     = acc[mi][ni][2] + b0;
            g_gi[(size_t)(r0 + 8) * K1 + c0 + 1] = acc[mi][ni][3] + b1;
        }
    }
}

__device__ __forceinline__ float fast_sigmoid(float x) {
    return __fdividef(1.0f, 1.0f + __expf(-x));
}
__device__ __forceinline__ float fast_tanh(float x) {
    // saturates correctly for large |x| (expf overflow -> 1, underflow -> -1)
    return 1.0f - __fdividef(2.0f, __expf(2.0f * x) + 1.0f);
}

// Elementwise GRU gates + touched-blend (float4; 256 blocks x 256 thr).
__global__ void gate_kernel(const float* __restrict__ memory, float* __restrict__ out) {
    int tid = blockIdx.x * 256 + threadIdx.x;   // 65536 = 1024 rows * 64 float4
    int n = tid >> 6, d4 = tid & 63;
    size_t base4 = (size_t)n * (K1 / 4);
    const float4* gi4 = (const float4*)g_gi;
    const float4* gh4 = (const float4*)g_gh;
    float4 ir  = gi4[base4 + d4];
    float4 iz  = gi4[base4 + 64 + d4];
    float4 in_ = gi4[base4 + 128 + d4];
    float4 hr  = gh4[base4 + d4];
    float4 hz  = gh4[base4 + 64 + d4];
    float4 hn  = gh4[base4 + 128 + d4];
    float4 h   = ((const float4*)memory)[(size_t)n * 64 + d4];
    bool touched = g_cnt[n] > 0.0f;
    float4 res;
#pragma unroll
    for (int c = 0; c < 4; c++) {
        float irc = ((const float*)&ir)[c], izc = ((const float*)&iz)[c];
        float inc = ((const float*)&in_)[c];
        float hrc = ((const float*)&hr)[c], hzc = ((const float*)&hz)[c];
        float hnc = ((const float*)&hn)[c];
        float hc  = ((const float*)&h)[c];
        float r  = fast_sigmoid(irc + hrc);
        float zz = fast_sigmoid(izc + hzc);
        float nn = fast_tanh(inc + r * hnc);
        ((float*)&res)[c] = touched ? ((1.0f - zz) * nn + zz * hc) : hc;
    }
    ((float4*)out)[(size_t)n * 64 + d4] = res;
}

// ---------------------------------------------------------------------------
extern "C" void kernel_launch(void* const* d_in, const int* in_sizes, int n_in,
                              void* d_out, int out_size) {
    const float* memory = (const float*)d_in[0];
    const int*   source = (const int*)d_in[1];
    const int*   target = (const int*)d_in[2];
    const float* dt     = (const float*)d_in[3];
    const float* sw1 = (const float*)d_in[4];
    const float* sb1 = (const float*)d_in[5];
    const float* sw2 = (const float*)d_in[6];
    const float* sb2 = (const float*)d_in[7];
    const float* tw1 = (const float*)d_in[8];
    const float* tb1 = (const float*)d_in[9];
    const float* tw2 = (const float*)d_in[10];
    const float* tb2 = (const float*)d_in[11];
    const float* wih = (const float*)d_in[12];
    const float* whh = (const float*)d_in[13];
    const float* bih = (const float*)d_in[14];
    const float* bhh = (const float*)d_in[15];
    float* out = (float*)d_out;

    mlp1_gh_kernel<<<320, 128>>>(sw1, sb1, tw1, tb1, memory, whh, bhh,
                                 source, target, dt);
    gemm2_kernel<<<dim3(2 * Bq / 64, Dd / 64), 128>>>(sw2, sb2, tw2, tb2, source, target);
    gi_kernel<<<dim3(Nn / 64, K1 / 64), 128>>>(wih, bih);
    gate_kernel<<<256, 256>>>(memory, out);
}